// round 12
// baseline (speedup 1.0000x reference)
#include <cuda_runtime.h>
#include <cuda_fp16.h>
#include <cstdint>

// ---------------- Problem constants ----------------
#define EMAX 100000
#define NNMAX 20000
#define BMAX 16
#define URED 256
#define USZ 4096
#define EH 1024
#define EOUT 512
#define NH 512
#define PCW 3072          // per-node precompute: [P_r 1024 | P_c 1024 | Qc 512 | Rx 512]

// ---------------- Scratch ----------------
__device__ __align__(16) float  g_urf[BMAX * URED];
__device__ __align__(16) __half g_xpad[NNMAX * 64];
__device__ __align__(16) __half g_pc[(size_t)NNMAX * PCW];
__device__ __align__(16) __half g_cu[BMAX * EH];
__device__ __align__(16) __half g_cu2[BMAX * NH];
__device__ __align__(16) __half g_wea[EH];
__device__ __align__(16) __half g_ha[(size_t)EMAX * EH];
__device__ __align__(16) __half g_hb[(size_t)EMAX * EH];
__device__ __align__(16) float  g_agg[(size_t)NNMAX * NH];
__device__ float g_cnt[NNMAX];
__device__ __align__(16) __half g_min[(size_t)NNMAX * NH];
__device__ float g_zbias[PCW];
__device__ int   g_is64;

// fp16 weights
__device__ __align__(16) __half g_w1[EH * EH];
__device__ __align__(16) __half g_w2[EH * EH];
__device__ __align__(16) __half g_w3[EH * EH];
__device__ __align__(16) __half g_w4[EOUT * EH];
__device__ __align__(16) __half g_wn0[NH * NH];
__device__ __align__(16) __half g_wn1[NH * NH];
__device__ __align__(16) __half g_wm0[NH * NH];
__device__ __align__(16) __half g_wpc[PCW * 64];

// ---------------- helpers ----------------
__device__ __forceinline__ uint32_t smem_u32(const void* p) {
    uint32_t a;
    asm("{ .reg .u64 t; cvta.to.shared.u64 t, %1; cvt.u32.u64 %0, t; }" : "=r"(a) : "l"(p));
    return a;
}
__device__ __forceinline__ uint32_t sw128(uint32_t off) { return off ^ ((off >> 3) & 0x70); }

__global__ void k_init_flag() { g_is64 = 1; }
__global__ void k_detect(const long long* __restrict__ p, int n, long long maxv) {
    int i = blockIdx.x * blockDim.x + threadIdx.x;
    if (i < n) { long long v = p[i]; if (v < 0 || v >= maxv) g_is64 = 0; }
}
__device__ __forceinline__ long long ld_idx(const void* p, long long i) {
    if (g_is64) return ((const long long*)p)[i];
    return (long long)((const int*)p)[i];
}

// ---------------- weight prep ----------------
__global__ void k_repack16(const float* __restrict__ src, __half* __restrict__ dst, int tot) {
    int i = blockIdx.x * blockDim.x + threadIdx.x;
    if (i < tot) dst[i] = __float2half_rn(src[i]);
}
__global__ void k_repsub(const float* __restrict__ src, __half* __restrict__ dst,
                         int rows, int pitch, int off) {
    int i = blockIdx.x * blockDim.x + threadIdx.x;
    if (i >= rows * 512) return;
    int j = i >> 9, k = i & 511;
    dst[i] = __float2half_rn(src[(size_t)j * pitch + off + k]);
}
__global__ void k_build_wpc(const float* __restrict__ ew0, const float* __restrict__ nw0,
                            const float* __restrict__ mw0) {
    int i = blockIdx.x * blockDim.x + threadIdx.x;
    if (i >= PCW * 64) return;
    int j = i >> 6, c = i & 63;
    float v = 0.f;
    if (c < 9) {
        if (j < 1024)      v = ew0[(size_t)j * 275 + c];
        else if (j < 2048) v = ew0[(size_t)(j - 1024) * 275 + 9 + c];
        else if (j < 2560) v = nw0[(size_t)(j - 2048) * 521 + c];
        else               v = mw0[(size_t)(j - 2560) * 777 + c];
    }
    g_wpc[i] = __float2half_rn(v);
}
__global__ void k_wea(const float* __restrict__ ew0) {
    int j = blockIdx.x * blockDim.x + threadIdx.x;
    if (j < EH) g_wea[j] = __float2half_rn(ew0[(size_t)j * 275 + 18]);
}

// ---------------- u reduction (fp32) + per-graph tables ----------------
__global__ void k_ur(const float* __restrict__ u, const float* __restrict__ w,
                     const float* __restrict__ bias, int B) {
    int wid = (blockIdx.x * blockDim.x + threadIdx.x) >> 5;
    int lane = threadIdx.x & 31;
    if (wid >= B * URED) return;
    int b = wid >> 8, j = wid & 255;
    const float* up = u + (size_t)b * USZ;
    const float* wp = w + (size_t)j * USZ;
    float s = 0.f;
    for (int k = lane; k < USZ; k += 32) s += up[k] * wp[k];
    #pragma unroll
    for (int o = 16; o; o >>= 1) s += __shfl_down_sync(0xffffffffu, s, o);
    if (lane == 0) g_urf[wid] = s + bias[j];
}
__global__ void k_cu(const float* __restrict__ ew0, const float* __restrict__ eb0) {
    int wid = (blockIdx.x * blockDim.x + threadIdx.x) >> 5;
    int lane = threadIdx.x & 31;
    if (wid >= BMAX * EH) return;
    int b = wid >> 10, j = wid & 1023;
    const float* up = g_urf + b * URED;
    const float* wp = ew0 + (size_t)j * 275 + 19;
    float s = 0.f;
    for (int k = lane; k < URED; k += 32) s += up[k] * wp[k];
    #pragma unroll
    for (int o = 16; o; o >>= 1) s += __shfl_down_sync(0xffffffffu, s, o);
    if (lane == 0) g_cu[wid] = __float2half_rn(s + eb0[j]);
}
__global__ void k_cu2(const float* __restrict__ mw0, const float* __restrict__ mb0) {
    int wid = (blockIdx.x * blockDim.x + threadIdx.x) >> 5;
    int lane = threadIdx.x & 31;
    if (wid >= BMAX * NH) return;
    int b = wid >> 9, j = wid & 511;
    const float* up = g_urf + b * URED;
    const float* wp = mw0 + (size_t)j * 777 + 521;
    float s = 0.f;
    for (int k = lane; k < URED; k += 32) s += up[k] * wp[k];
    #pragma unroll
    for (int o = 16; o; o >>= 1) s += __shfl_down_sync(0xffffffffu, s, o);
    if (lane == 0) g_cu2[wid] = __float2half_rn(s + mb0[j]);
}

// ---------------- x -> fp16 padded [Nn x 64] ----------------
__global__ void k_xpad(const float* __restrict__ x, int Nn) {
    int i = blockIdx.x * blockDim.x + threadIdx.x;
    if (i >= Nn * 64) return;
    int n = i >> 6, c = i & 63;
    g_xpad[i] = (c < 9) ? __float2half_rn(x[(size_t)n * 9 + c]) : __half(0.f);
}

// ---------------- edge layer-0 (gather-add) + fused degree count ----------------
__global__ void k_edge0(const void* __restrict__ eidx, const float* __restrict__ ea,
                        const void* __restrict__ batch, __half* __restrict__ out, int E) {
    int e = (blockIdx.x * blockDim.x + threadIdx.x) >> 5;
    int lane = threadIdx.x & 31;
    if (e >= E) return;
    long long row = ld_idx(eidx, e);
    long long col = ld_idx(eidx, (long long)E + e);
    long long b = ld_idx(batch, row);
    if (lane == 0) atomicAdd(&g_cnt[row], 1.f);
    float eav = ea[e];
    const uint4* pr = (const uint4*)(g_pc + row * PCW);
    const uint4* pc = (const uint4*)(g_pc + col * PCW + 1024);
    const uint4* cu = (const uint4*)(g_cu + b * EH);
    const uint4* we = (const uint4*)g_wea;
    uint4* o = (uint4*)(out + (size_t)e * EH);
    #pragma unroll
    for (int i = 0; i < 4; i++) {
        int q = lane + i * 32;
        uint4 a4 = pr[q], b4 = pc[q], c4 = cu[q], w4 = we[q], r4;
        const __half2* ah = (const __half2*)&a4;
        const __half2* bh = (const __half2*)&b4;
        const __half2* ch = (const __half2*)&c4;
        const __half2* wh = (const __half2*)&w4;
        __half2* rh = (__half2*)&r4;
        #pragma unroll
        for (int c = 0; c < 4; c++) {
            float2 fa = __half22float2(ah[c]), fb = __half22float2(bh[c]);
            float2 fc = __half22float2(ch[c]), fw = __half22float2(wh[c]);
            float v0 = fa.x + fb.x + fc.x + eav * fw.x;
            float v1 = fa.y + fb.y + fc.y + eav * fw.y;
            v0 = v0 > 0.f ? v0 : 0.f; v1 = v1 > 0.f ? v1 : 0.f;
            rh[c] = __floats2half2_rn(v0, v1);
        }
        o[q] = r4;
    }
}

// ---------------- fp16 HMMA GEMM: CTA 128x128, warp 32x64, 3-stage pipeline ----------------
#define HTILE 16384
#define STG (2 * HTILE)            // one stage: A(16K) + B(16K)
#define H_SMEM (3 * STG)           // 96 KB

__device__ __forceinline__ void ldm4(uint32_t* r, uint32_t addr) {
    asm volatile("ldmatrix.sync.aligned.m8n8.x4.shared.b16 {%0,%1,%2,%3}, [%4];"
                 : "=r"(r[0]), "=r"(r[1]), "=r"(r[2]), "=r"(r[3]) : "r"(addr));
}
__device__ __forceinline__ void mma16(float* d, const uint32_t* a, const uint32_t* b) {
    asm volatile(
        "mma.sync.aligned.m16n8k16.row.col.f32.f16.f16.f32 "
        "{%0,%1,%2,%3}, {%4,%5,%6,%7}, {%8,%9}, {%0,%1,%2,%3};"
        : "+f"(d[0]), "+f"(d[1]), "+f"(d[2]), "+f"(d[3])
        : "r"(a[0]), "r"(a[1]), "r"(a[2]), "r"(a[3]), "r"(b[0]), "r"(b[1]));
}

// MODE: 0=std store; 1=store + gather pc[idx[m]][2048+n]; 2=relu->red.v2 into agg[idx[m]];
//       3=store + pc[m][2560+n] + cu2[batch[m]][n], no bias;
//       4=MODE3 math + in-register dot with bias(=mw1) -> atomicAdd out[m] (final layer fused)
template <int MODE, bool RELU>
__global__ void __launch_bounds__(256)
k_g(const __half* __restrict__ A, const __half* __restrict__ W,
    const float* __restrict__ bias, void* __restrict__ Cv,
    int M, int Ntot, int K,
    const void* __restrict__ idx, long long idxoff,
    const __half* __restrict__ pc, const __half* __restrict__ cu2,
    const void* __restrict__ batch) {
    extern __shared__ char smem[];
    const uint32_t s0 = smem_u32(smem);

    const int tid = threadIdx.x;
    const int lane = tid & 31, wid = tid >> 5;
    const int warpM = wid & 3, warpN = wid >> 2;
    const size_t bm = (size_t)blockIdx.y * 128;
    const int bn = blockIdx.x * 128;
    const int nk = K >> 6;

    const int cc = tid & 7, r0 = tid >> 3;
    const int a_row = warpM * 32 + (lane & 15);
    const int a_kb  = (lane >> 4) * 16;
    const int b_row = warpN * 64 + ((lane >> 4) << 3) + (lane & 7);
    const int b_kb  = ((lane >> 3) & 1) * 16;

    float acc[2][8][4];
    #pragma unroll
    for (int i = 0; i < 2; i++)
        #pragma unroll
        for (int j = 0; j < 8; j++)
            #pragma unroll
            for (int r = 0; r < 4; r++) acc[i][j][r] = 0.f;

    auto copy_stage = [&](int kb, int buf) {
        const int kB = kb * 128;
        const uint32_t base = s0 + buf * STG;
        #pragma unroll
        for (int i = 0; i < 4; i++) {
            int r = r0 + i * 32;
            size_t mg = bm + r;
            int ok = (mg < (size_t)M) ? 16 : 0;
            const char* src = (const char*)(A + (mg < (size_t)M ? mg : 0) * K) + kB + cc * 16;
            uint32_t dst = base + sw128(r * 128 + cc * 16);
            asm volatile("cp.async.cg.shared.global [%0], [%1], 16, %2;"
                         :: "r"(dst), "l"(src), "r"(ok));
        }
        #pragma unroll
        for (int i = 0; i < 4; i++) {
            int r = r0 + i * 32;
            const char* src = (const char*)(W + (size_t)(bn + r) * K) + kB + cc * 16;
            uint32_t dst = base + HTILE + sw128(r * 128 + cc * 16);
            asm volatile("cp.async.cg.shared.global [%0], [%1], 16;" :: "r"(dst), "l"(src));
        }
        asm volatile("cp.async.commit_group;" ::: "memory");
    };

    // prologue: stages 0,1 (in-order group retirement makes the empty-group case safe)
    copy_stage(0, 0);
    if (nk > 1) copy_stage(1, 1);
    else        asm volatile("cp.async.commit_group;" ::: "memory");
    asm volatile("cp.async.wait_group 1;" ::: "memory");
    __syncthreads();

    for (int kb = 0; kb < nk; kb++) {
        // issue copy two stages ahead (buf (kb+2)%3 held stage kb-1: all warps done per last sync)
        if (kb + 2 < nk) copy_stage(kb + 2, (kb + 2) % 3);
        else             asm volatile("cp.async.commit_group;" ::: "memory");

        const uint32_t Ab = s0 + (kb % 3) * STG;
        const uint32_t Bb = Ab + HTILE;
        #pragma unroll
        for (int s = 0; s < 4; s++) {
            const int ks = s * 32;
            uint32_t a[2][4];
            #pragma unroll
            for (int mt = 0; mt < 2; mt++)
                ldm4(a[mt], Ab + sw128((a_row + mt * 16) * 128 + ks + a_kb));
            #pragma unroll
            for (int p = 0; p < 4; p++) {
                uint32_t b[4];
                ldm4(b, Bb + sw128((b_row + p * 16) * 128 + ks + b_kb));
                #pragma unroll
                for (int mt = 0; mt < 2; mt++) {
                    mma16(acc[mt][2 * p],     a[mt], b);
                    mma16(acc[mt][2 * p + 1], a[mt], b + 2);
                }
            }
        }

        asm volatile("cp.async.wait_group 1;" ::: "memory");  // stage kb+1 ready
        __syncthreads();
    }

    __half* C = (__half*)Cv;
    float* Fout = (float*)Cv;
    const int qrow = lane >> 2, qcol = (lane & 3) * 2;
    #pragma unroll
    for (int mt = 0; mt < 2; mt++) {
        #pragma unroll
        for (int hf = 0; hf < 2; hf++) {
            size_t r = bm + warpM * 32 + mt * 16 + qrow + hf * 8;
            bool okr = r < (size_t)M;
            if (MODE != 4 && !okr) continue;
            long long t = 0, bb = 0;
            if ((MODE == 1 || MODE == 2) && okr) t = ld_idx(idx, idxoff + (long long)r);
            if ((MODE == 3 || MODE == 4) && okr) bb = ld_idx(batch, (long long)r);
            float partial = 0.f;
            #pragma unroll
            for (int nt = 0; nt < 8; nt++) {
                int col = bn + warpN * 64 + nt * 8 + qcol;
                float v0 = acc[mt][nt][hf * 2 + 0];
                float v1 = acc[mt][nt][hf * 2 + 1];
                if (MODE == 0 || MODE == 1 || MODE == 2) { v0 += bias[col]; v1 += bias[col + 1]; }
                if (MODE == 1) {
                    float2 g = __half22float2(*(const __half2*)(pc + (size_t)t * PCW + 2048 + col));
                    v0 += g.x; v1 += g.y;
                }
                if (MODE == 3 || MODE == 4) {
                    float2 g = okr ? __half22float2(*(const __half2*)(pc + r * PCW + 2560 + col))
                                   : make_float2(0.f, 0.f);
                    float2 c2 = okr ? __half22float2(*(const __half2*)(cu2 + bb * NH + col))
                                    : make_float2(0.f, 0.f);
                    v0 += g.x + c2.x; v1 += g.y + c2.y;
                }
                if (RELU) { v0 = v0 > 0.f ? v0 : 0.f; v1 = v1 > 0.f ? v1 : 0.f; }
                if (MODE == 4) {
                    partial += v0 * bias[col] + v1 * bias[col + 1];   // bias = mw1
                } else if (MODE == 2) {
                    float* p = Fout + (size_t)t * Ntot + col;
                    asm volatile("red.global.add.v2.f32 [%0], {%1,%2};"
                                 :: "l"(p), "f"(v0), "f"(v1) : "memory");
                } else {
                    *(__half2*)(C + r * (size_t)Ntot + col) = __floats2half2_rn(v0, v1);
                }
            }
            if (MODE == 4) {
                partial += __shfl_xor_sync(0xffffffffu, partial, 1);
                partial += __shfl_xor_sync(0xffffffffu, partial, 2);
                if (okr && (lane & 3) == 0) atomicAdd(Fout + r, partial);
            }
        }
    }
}

// ---------------- misc small kernels ----------------
__global__ void k_zero(float* p, int n) {
    int i = blockIdx.x * blockDim.x + threadIdx.x;
    if (i < n) p[i] = 0.f;
}
__global__ void k_zero4(float4* p, int n4) {
    int i = blockIdx.x * blockDim.x + threadIdx.x;
    if (i < n4) p[i] = make_float4(0.f, 0.f, 0.f, 0.f);
}
__global__ void k_outinit(float* out, const float* mb1, int Nn) {
    int i = blockIdx.x * blockDim.x + threadIdx.x;
    if (i < Nn) out[i] = mb1[0];
}
__global__ void k_norm(int Nn) {
    int n = (blockIdx.x * blockDim.x + threadIdx.x) >> 5;
    int lane = threadIdx.x & 31;
    if (n >= Nn) return;
    float c = g_cnt[n];
    float inv = 1.f / (c < 1.f ? 1.f : c);
    const float2* a = (const float2*)(g_agg + (size_t)n * NH);
    __half2* o = (__half2*)(g_min + (size_t)n * NH);
    #pragma unroll
    for (int i = 0; i < 8; i++) {
        int j = lane + i * 32;
        float2 v = a[j];
        o[j] = __floats2half2_rn(v.x * inv, v.y * inv);
    }
}

// ---------------- host ----------------
static void* sym(const void* s) { void* p = nullptr; cudaGetSymbolAddress(&p, s); return p; }

template <int MODE, bool RELU>
static void run_g(const __half* A, const __half* W, const float* bias, void* C,
                  int M, int Ntot, int K,
                  const void* idx = nullptr, long long idxoff = 0,
                  const __half* pc = nullptr, const __half* cu2 = nullptr,
                  const void* batch = nullptr) {
    static bool attr_done = false;
    if (!attr_done) {
        cudaFuncSetAttribute(k_g<MODE, RELU>, cudaFuncAttributeMaxDynamicSharedMemorySize, H_SMEM);
        attr_done = true;
    }
    dim3 grid(Ntot / 128, (M + 127) / 128);
    k_g<MODE, RELU><<<grid, 256, H_SMEM>>>(A, W, bias, C, M, Ntot, K, idx, idxoff, pc, cu2, batch);
}

extern "C" void kernel_launch(void* const* d_in, const int* in_sizes, int n_in,
                              void* d_out, int out_size) {
    const float* x    = (const float*)d_in[0];
    const void*  eidx = d_in[1];
    const float* ea   = (const float*)d_in[2];
    const float* u    = (const float*)d_in[3];
    const void*  bat  = d_in[4];
    const float* w_sel = (const float*)d_in[5];
    const float* b_sel = (const float*)d_in[6];
    const float* ew0 = (const float*)d_in[7];  const float* eb0 = (const float*)d_in[8];
    const float* ew1 = (const float*)d_in[9];  const float* eb1 = (const float*)d_in[10];
    const float* ew2 = (const float*)d_in[11]; const float* eb2 = (const float*)d_in[12];
    const float* ew3 = (const float*)d_in[13]; const float* eb3 = (const float*)d_in[14];
    const float* ew4 = (const float*)d_in[15]; const float* eb4 = (const float*)d_in[16];
    const float* nw0 = (const float*)d_in[17]; const float* nb0 = (const float*)d_in[18];
    const float* nw1 = (const float*)d_in[19]; const float* nb1 = (const float*)d_in[20];
    const float* mw0 = (const float*)d_in[21]; const float* mb0 = (const float*)d_in[22];
    const float* mw1 = (const float*)d_in[23]; const float* mb1 = (const float*)d_in[24];
    float* out = (float*)d_out;

    const int Nn = in_sizes[0] / 9;
    const int E  = in_sizes[1] / 2;
    const int B  = in_sizes[3] / USZ;

    __half* p_xpad = (__half*)sym(g_xpad);
    __half* p_pc   = (__half*)sym(g_pc);
    __half* p_ha = (__half*)sym(g_ha);
    __half* p_hb = (__half*)sym(g_hb);
    __half* p_min = (__half*)sym(g_min);
    __half* p_cu2 = (__half*)sym(g_cu2);
    float*  p_agg = (float*)sym(g_agg);
    float*  p_cnt = (float*)sym(g_cnt);
    float*  p_zb  = (float*)sym(g_zbias);
    __half* p_w1 = (__half*)sym(g_w1); __half* p_w2 = (__half*)sym(g_w2);
    __half* p_w3 = (__half*)sym(g_w3); __half* p_w4 = (__half*)sym(g_w4);
    __half* p_wn0 = (__half*)sym(g_wn0); __half* p_wn1 = (__half*)sym(g_wn1);
    __half* p_wm0 = (__half*)sym(g_wm0); __half* p_wpc = (__half*)sym(g_wpc);

    // 0. dtype detect; weight prep
    k_init_flag<<<1, 1>>>();
    k_detect<<<(E + 255) / 256, 256>>>((const long long*)eidx, E, (long long)Nn);
    k_zero<<<(PCW + 255) / 256, 256>>>(p_zb, PCW);
    k_repack16<<<(EH * EH + 255) / 256, 256>>>(ew1, p_w1, EH * EH);
    k_repack16<<<(EH * EH + 255) / 256, 256>>>(ew2, p_w2, EH * EH);
    k_repack16<<<(EH * EH + 255) / 256, 256>>>(ew3, p_w3, EH * EH);
    k_repack16<<<(EOUT * EH + 255) / 256, 256>>>(ew4, p_w4, EOUT * EH);
    k_repack16<<<(NH * NH + 255) / 256, 256>>>(nw1, p_wn1, NH * NH);
    k_repsub<<<(NH * 512 + 255) / 256, 256>>>(nw0, p_wn0, NH, 521, 9);
    k_repsub<<<(NH * 512 + 255) / 256, 256>>>(mw0, p_wm0, NH, 777, 9);
    k_build_wpc<<<(PCW * 64 + 255) / 256, 256>>>(ew0, nw0, mw0);
    k_wea<<<(EH + 255) / 256, 256>>>(ew0);

    // 1. u_r + per-graph tables
    k_ur<<<(B * URED * 32 + 255) / 256, 256>>>(u, w_sel, b_sel, B);
    k_cu<<<(BMAX * EH * 32 + 255) / 256, 256>>>(ew0, eb0);
    k_cu2<<<(BMAX * NH * 32 + 255) / 256, 256>>>(mw0, mb0);

    // 2. per-node precompute: [Pr | Pc | Qc | Rx] = xpad @ wpc^T
    k_xpad<<<(Nn * 64 + 255) / 256, 256>>>(x, Nn);
    run_g<0, false>(p_xpad, p_wpc, p_zb, p_pc, Nn, PCW, 64);

    // 3. edge layer 0 (gather-add, fused degree count) -> g_ha
    k_zero<<<(Nn + 255) / 256, 256>>>(p_cnt, Nn);
    k_edge0<<<(E * 32 + 255) / 256, 256>>>(eidx, ea, bat, p_ha, E);

    // 4. edge MLP layers 1-4
    run_g<0, true >(p_ha, p_w1, eb1, p_hb, E, EH, EH);
    run_g<0, true >(p_hb, p_w2, eb2, p_ha, E, EH, EH);
    run_g<0, true >(p_ha, p_w3, eb3, p_hb, E, EH, EH);
    run_g<0, false>(p_hb, p_w4, eb4, p_ha, E, EOUT, EH);       // edge_out, pitch 512

    // 5. node MLP1 layer 0: eout @ wn0 + Qc[col] gather
    run_g<1, true>(p_ha, p_wn0, nb0, p_hb, E, NH, NH, eidx, (long long)E, p_pc);

    // 6. node MLP1 layer 1 with fused scatter-add into agg[row]
    k_zero4<<<(Nn * NH / 4 + 255) / 256, 256>>>((float4*)p_agg, Nn * NH / 4);
    run_g<2, true>(p_hb, p_wn1, nb1, p_agg, E, NH, NH, eidx, 0);

    // 7. scatter-mean normalize -> fp16
    k_norm<<<(Nn * 32 + 255) / 256, 256>>>(Nn);

    // 8. node MLP2 with fused final 512->1 dot (bias param carries mw1)
    k_outinit<<<(Nn + 255) / 256, 256>>>(out, mb1, Nn);
    run_g<4, true>(p_min, p_wm0, mw1, out, Nn, NH, NH, nullptr, 0, p_pc, p_cu2, bat);
}

// round 14
// speedup vs baseline: 1.5696x; 1.5696x over previous
#include <cuda_runtime.h>
#include <cuda_fp16.h>
#include <cstdint>

// ---------------- Problem constants ----------------
#define EMAX 100000
#define NNMAX 20000
#define BMAX 16
#define URED 256
#define USZ 4096
#define EH 1024
#define EOUT 512
#define NH 512
#define PCW 3072          // per-node precompute: [P_r 1024 | P_c 1024 | Qc 512 | Rx 512]

// ---------------- Scratch ----------------
__device__ __align__(16) float  g_urf[BMAX * URED];
__device__ __align__(16) __half g_xpad[NNMAX * 64];
__device__ __align__(16) __half g_pc[(size_t)NNMAX * PCW];
__device__ __align__(16) __half g_cu[BMAX * EH];
__device__ __align__(16) __half g_cu2[BMAX * NH];
__device__ __align__(16) __half g_wea[EH];
__device__ __align__(16) __half g_ha[(size_t)EMAX * EH];
__device__ __align__(16) __half g_hb[(size_t)EMAX * EH];
__device__ __align__(16) float  g_agg[(size_t)NNMAX * NH];
__device__ float g_cnt[NNMAX];
__device__ __align__(16) __half g_min[(size_t)NNMAX * NH];
__device__ float g_zbias[PCW];
__device__ int   g_is64;

// fp16 weights
__device__ __align__(16) __half g_w1[EH * EH];
__device__ __align__(16) __half g_w2[EH * EH];
__device__ __align__(16) __half g_w3[EH * EH];
__device__ __align__(16) __half g_w4[EOUT * EH];
__device__ __align__(16) __half g_wn0[NH * NH];
__device__ __align__(16) __half g_wn1[NH * NH];
__device__ __align__(16) __half g_wm0[NH * NH];
__device__ __align__(16) __half g_wpc[PCW * 64];

// ---------------- helpers ----------------
__device__ __forceinline__ uint32_t smem_u32(const void* p) {
    uint32_t a;
    asm("{ .reg .u64 t; cvta.to.shared.u64 t, %1; cvt.u32.u64 %0, t; }" : "=r"(a) : "l"(p));
    return a;
}
__device__ __forceinline__ uint32_t sw128(uint32_t off) { return off ^ ((off >> 3) & 0x70); }

__global__ void k_init_flag() { g_is64 = 1; }
__global__ void k_detect(const long long* __restrict__ p, int n, long long maxv) {
    int i = blockIdx.x * blockDim.x + threadIdx.x;
    if (i < n) { long long v = p[i]; if (v < 0 || v >= maxv) g_is64 = 0; }
}
__device__ __forceinline__ long long ld_idx(const void* p, long long i) {
    if (g_is64) return ((const long long*)p)[i];
    return (long long)((const int*)p)[i];
}

// ---------------- weight prep ----------------
__global__ void k_repack16(const float* __restrict__ src, __half* __restrict__ dst, int tot) {
    int i = blockIdx.x * blockDim.x + threadIdx.x;
    if (i < tot) dst[i] = __float2half_rn(src[i]);
}
__global__ void k_repsub(const float* __restrict__ src, __half* __restrict__ dst,
                         int rows, int pitch, int off) {
    int i = blockIdx.x * blockDim.x + threadIdx.x;
    if (i >= rows * 512) return;
    int j = i >> 9, k = i & 511;
    dst[i] = __float2half_rn(src[(size_t)j * pitch + off + k]);
}
__global__ void k_build_wpc(const float* __restrict__ ew0, const float* __restrict__ nw0,
                            const float* __restrict__ mw0) {
    int i = blockIdx.x * blockDim.x + threadIdx.x;
    if (i >= PCW * 64) return;
    int j = i >> 6, c = i & 63;
    float v = 0.f;
    if (c < 9) {
        if (j < 1024)      v = ew0[(size_t)j * 275 + c];
        else if (j < 2048) v = ew0[(size_t)(j - 1024) * 275 + 9 + c];
        else if (j < 2560) v = nw0[(size_t)(j - 2048) * 521 + c];
        else               v = mw0[(size_t)(j - 2560) * 777 + c];
    }
    g_wpc[i] = __float2half_rn(v);
}
__global__ void k_wea(const float* __restrict__ ew0) {
    int j = blockIdx.x * blockDim.x + threadIdx.x;
    if (j < EH) g_wea[j] = __float2half_rn(ew0[(size_t)j * 275 + 18]);
}

// ---------------- u reduction (fp32) + per-graph tables ----------------
__global__ void k_ur(const float* __restrict__ u, const float* __restrict__ w,
                     const float* __restrict__ bias, int B) {
    int wid = (blockIdx.x * blockDim.x + threadIdx.x) >> 5;
    int lane = threadIdx.x & 31;
    if (wid >= B * URED) return;
    int b = wid >> 8, j = wid & 255;
    const float* up = u + (size_t)b * USZ;
    const float* wp = w + (size_t)j * USZ;
    float s = 0.f;
    for (int k = lane; k < USZ; k += 32) s += up[k] * wp[k];
    #pragma unroll
    for (int o = 16; o; o >>= 1) s += __shfl_down_sync(0xffffffffu, s, o);
    if (lane == 0) g_urf[wid] = s + bias[j];
}
__global__ void k_cu(const float* __restrict__ ew0, const float* __restrict__ eb0) {
    int wid = (blockIdx.x * blockDim.x + threadIdx.x) >> 5;
    int lane = threadIdx.x & 31;
    if (wid >= BMAX * EH) return;
    int b = wid >> 10, j = wid & 1023;
    const float* up = g_urf + b * URED;
    const float* wp = ew0 + (size_t)j * 275 + 19;
    float s = 0.f;
    for (int k = lane; k < URED; k += 32) s += up[k] * wp[k];
    #pragma unroll
    for (int o = 16; o; o >>= 1) s += __shfl_down_sync(0xffffffffu, s, o);
    if (lane == 0) g_cu[wid] = __float2half_rn(s + eb0[j]);
}
__global__ void k_cu2(const float* __restrict__ mw0, const float* __restrict__ mb0) {
    int wid = (blockIdx.x * blockDim.x + threadIdx.x) >> 5;
    int lane = threadIdx.x & 31;
    if (wid >= BMAX * NH) return;
    int b = wid >> 9, j = wid & 511;
    const float* up = g_urf + b * URED;
    const float* wp = mw0 + (size_t)j * 777 + 521;
    float s = 0.f;
    for (int k = lane; k < URED; k += 32) s += up[k] * wp[k];
    #pragma unroll
    for (int o = 16; o; o >>= 1) s += __shfl_down_sync(0xffffffffu, s, o);
    if (lane == 0) g_cu2[wid] = __float2half_rn(s + mb0[j]);
}

// ---------------- x -> fp16 padded [Nn x 64] ----------------
__global__ void k_xpad(const float* __restrict__ x, int Nn) {
    int i = blockIdx.x * blockDim.x + threadIdx.x;
    if (i >= Nn * 64) return;
    int n = i >> 6, c = i & 63;
    g_xpad[i] = (c < 9) ? __float2half_rn(x[(size_t)n * 9 + c]) : __half(0.f);
}

// ---------------- edge layer-0 (gather-add) + fused degree count ----------------
__global__ void k_edge0(const void* __restrict__ eidx, const float* __restrict__ ea,
                        const void* __restrict__ batch, __half* __restrict__ out, int E) {
    int e = (blockIdx.x * blockDim.x + threadIdx.x) >> 5;
    int lane = threadIdx.x & 31;
    if (e >= E) return;
    long long row = ld_idx(eidx, e);
    long long col = ld_idx(eidx, (long long)E + e);
    long long b = ld_idx(batch, row);
    if (lane == 0) atomicAdd(&g_cnt[row], 1.f);
    float eav = ea[e];
    const uint4* pr = (const uint4*)(g_pc + row * PCW);
    const uint4* pc = (const uint4*)(g_pc + col * PCW + 1024);
    const uint4* cu = (const uint4*)(g_cu + b * EH);
    const uint4* we = (const uint4*)g_wea;
    uint4* o = (uint4*)(out + (size_t)e * EH);
    #pragma unroll
    for (int i = 0; i < 4; i++) {
        int q = lane + i * 32;
        uint4 a4 = pr[q], b4 = pc[q], c4 = cu[q], w4 = we[q], r4;
        const __half2* ah = (const __half2*)&a4;
        const __half2* bh = (const __half2*)&b4;
        const __half2* ch = (const __half2*)&c4;
        const __half2* wh = (const __half2*)&w4;
        __half2* rh = (__half2*)&r4;
        #pragma unroll
        for (int c = 0; c < 4; c++) {
            float2 fa = __half22float2(ah[c]), fb = __half22float2(bh[c]);
            float2 fc = __half22float2(ch[c]), fw = __half22float2(wh[c]);
            float v0 = fa.x + fb.x + fc.x + eav * fw.x;
            float v1 = fa.y + fb.y + fc.y + eav * fw.y;
            v0 = v0 > 0.f ? v0 : 0.f; v1 = v1 > 0.f ? v1 : 0.f;
            rh[c] = __floats2half2_rn(v0, v1);
        }
        o[q] = r4;
    }
}

// ---------------- fp16 HMMA GEMM: CTA 128x128, warp 32x64, 2-stage (R11 proven) ----------------
#define HTILE 16384
#define H_SMEM (4 * HTILE)         // 64 KB -> 3 CTAs/SM

__device__ __forceinline__ void ldm4(uint32_t* r, uint32_t addr) {
    asm volatile("ldmatrix.sync.aligned.m8n8.x4.shared.b16 {%0,%1,%2,%3}, [%4];"
                 : "=r"(r[0]), "=r"(r[1]), "=r"(r[2]), "=r"(r[3]) : "r"(addr));
}
__device__ __forceinline__ void mma16(float* d, const uint32_t* a, const uint32_t* b) {
    asm volatile(
        "mma.sync.aligned.m16n8k16.row.col.f32.f16.f16.f32 "
        "{%0,%1,%2,%3}, {%4,%5,%6,%7}, {%8,%9}, {%0,%1,%2,%3};"
        : "+f"(d[0]), "+f"(d[1]), "+f"(d[2]), "+f"(d[3])
        : "r"(a[0]), "r"(a[1]), "r"(a[2]), "r"(a[3]), "r"(b[0]), "r"(b[1]));
}

// MODE: 0=std store; 1=store + gather pc[idx[m]][2048+n]; 2=relu->red.v2 into agg[idx[m]];
//       4=pc[m][2560+n] + cu2[batch[m]][n] + in-register dot with bias(=mw1) -> atomicAdd out[m]
template <int MODE, bool RELU>
__global__ void __launch_bounds__(256)
k_g(const __half* __restrict__ A, const __half* __restrict__ W,
    const float* __restrict__ bias, void* __restrict__ Cv,
    int M, int Ntot, int K,
    const void* __restrict__ idx, long long idxoff,
    const __half* __restrict__ pc, const __half* __restrict__ cu2,
    const void* __restrict__ batch) {
    extern __shared__ char smem[];
    const uint32_t s_as = smem_u32(smem);
    const uint32_t s_bs = s_as + 2 * HTILE;

    const int tid = threadIdx.x;
    const int lane = tid & 31, wid = tid >> 5;
    const int warpM = wid & 3, warpN = wid >> 2;
    const size_t bm = (size_t)blockIdx.y * 128;
    const int bn = blockIdx.x * 128;
    const int nk = K >> 6;

    const int cc = tid & 7, r0 = tid >> 3;
    const int a_row = warpM * 32 + (lane & 15);
    const int a_kb  = (lane >> 4) * 16;
    const int b_row = warpN * 64 + ((lane >> 4) << 3) + (lane & 7);
    const int b_kb  = ((lane >> 3) & 1) * 16;

    float acc[2][8][4];
    #pragma unroll
    for (int i = 0; i < 2; i++)
        #pragma unroll
        for (int j = 0; j < 8; j++)
            #pragma unroll
            for (int r = 0; r < 4; r++) acc[i][j][r] = 0.f;

    auto copy_stage = [&](int kb, int buf) {
        const int kB = kb * 128;
        #pragma unroll
        for (int i = 0; i < 4; i++) {
            int r = r0 + i * 32;
            size_t mg = bm + r;
            int ok = (mg < (size_t)M) ? 16 : 0;
            const char* src = (const char*)(A + (mg < (size_t)M ? mg : 0) * K) + kB + cc * 16;
            uint32_t dst = s_as + buf * HTILE + sw128(r * 128 + cc * 16);
            asm volatile("cp.async.cg.shared.global [%0], [%1], 16, %2;"
                         :: "r"(dst), "l"(src), "r"(ok));
        }
        #pragma unroll
        for (int i = 0; i < 4; i++) {
            int r = r0 + i * 32;
            const char* src = (const char*)(W + (size_t)(bn + r) * K) + kB + cc * 16;
            uint32_t dst = s_bs + buf * HTILE + sw128(r * 128 + cc * 16);
            asm volatile("cp.async.cg.shared.global [%0], [%1], 16;" :: "r"(dst), "l"(src));
        }
        asm volatile("cp.async.commit_group;" ::: "memory");
    };

    copy_stage(0, 0);

    for (int kb = 0; kb < nk; kb++) {
        asm volatile("cp.async.wait_group 0;" ::: "memory");
        __syncthreads();
        if (kb + 1 < nk) copy_stage(kb + 1, (kb + 1) & 1);

        const uint32_t Ab = s_as + (kb & 1) * HTILE;
        const uint32_t Bb = s_bs + (kb & 1) * HTILE;

        #pragma unroll
        for (int s = 0; s < 4; s++) {
            const int ks = s * 32;
            uint32_t a[2][4];
            #pragma unroll
            for (int mt = 0; mt < 2; mt++)
                ldm4(a[mt], Ab + sw128((a_row + mt * 16) * 128 + ks + a_kb));
            #pragma unroll
            for (int p = 0; p < 4; p++) {
                uint32_t b[4];
                ldm4(b, Bb + sw128((b_row + p * 16) * 128 + ks + b_kb));
                #pragma unroll
                for (int mt = 0; mt < 2; mt++) {
                    mma16(acc[mt][2 * p],     a[mt], b);
                    mma16(acc[mt][2 * p + 1], a[mt], b + 2);
                }
            }
        }
        __syncthreads();
    }

    __half* C = (__half*)Cv;
    float* Fout = (float*)Cv;
    const int qrow = lane >> 2, qcol = (lane & 3) * 2;
    #pragma unroll
    for (int mt = 0; mt < 2; mt++) {
        #pragma unroll
        for (int hf = 0; hf < 2; hf++) {
            size_t r = bm + warpM * 32 + mt * 16 + qrow + hf * 8;
            bool okr = r < (size_t)M;
            if (MODE != 4 && !okr) continue;
            long long t = 0, bb = 0;
            if ((MODE == 1 || MODE == 2) && okr) t = ld_idx(idx, idxoff + (long long)r);
            if (MODE == 4 && okr) bb = ld_idx(batch, (long long)r);
            float partial = 0.f;
            #pragma unroll
            for (int nt = 0; nt < 8; nt++) {
                int col = bn + warpN * 64 + nt * 8 + qcol;
                float v0 = acc[mt][nt][hf * 2 + 0];
                float v1 = acc[mt][nt][hf * 2 + 1];
                if (MODE != 4) { v0 += bias[col]; v1 += bias[col + 1]; }
                if (MODE == 1) {
                    float2 g = __half22float2(*(const __half2*)(pc + (size_t)t * PCW + 2048 + col));
                    v0 += g.x; v1 += g.y;
                }
                if (MODE == 4) {
                    float2 g = okr ? __half22float2(*(const __half2*)(pc + r * PCW + 2560 + col))
                                   : make_float2(0.f, 0.f);
                    float2 c2 = okr ? __half22float2(*(const __half2*)(cu2 + bb * NH + col))
                                    : make_float2(0.f, 0.f);
                    v0 += g.x + c2.x; v1 += g.y + c2.y;
                }
                if (RELU) { v0 = v0 > 0.f ? v0 : 0.f; v1 = v1 > 0.f ? v1 : 0.f; }
                if (MODE == 4) {
                    partial += v0 * bias[col] + v1 * bias[col + 1];   // bias = mw1
                } else if (MODE == 2) {
                    float* p = Fout + (size_t)t * Ntot + col;
                    asm volatile("red.global.add.v2.f32 [%0], {%1,%2};"
                                 :: "l"(p), "f"(v0), "f"(v1) : "memory");
                } else {
                    *(__half2*)(C + r * (size_t)Ntot + col) = __floats2half2_rn(v0, v1);
                }
            }
            if (MODE == 4) {
                partial += __shfl_xor_sync(0xffffffffu, partial, 1);
                partial += __shfl_xor_sync(0xffffffffu, partial, 2);
                if (okr && (lane & 3) == 0) atomicAdd(Fout + r, partial);
            }
        }
    }
}

// ---------------- misc small kernels ----------------
__global__ void k_zero(float* p, int n) {
    int i = blockIdx.x * blockDim.x + threadIdx.x;
    if (i < n) p[i] = 0.f;
}
__global__ void k_zero4(float4* p, int n4) {
    int i = blockIdx.x * blockDim.x + threadIdx.x;
    if (i < n4) p[i] = make_float4(0.f, 0.f, 0.f, 0.f);
}
__global__ void k_outinit(float* out, const float* mb1, int Nn) {
    int i = blockIdx.x * blockDim.x + threadIdx.x;
    if (i < Nn) out[i] = mb1[0];
}
__global__ void k_norm(int Nn) {
    int n = (blockIdx.x * blockDim.x + threadIdx.x) >> 5;
    int lane = threadIdx.x & 31;
    if (n >= Nn) return;
    float c = g_cnt[n];
    float inv = 1.f / (c < 1.f ? 1.f : c);
    const float2* a = (const float2*)(g_agg + (size_t)n * NH);
    __half2* o = (__half2*)(g_min + (size_t)n * NH);
    #pragma unroll
    for (int i = 0; i < 8; i++) {
        int j = lane + i * 32;
        float2 v = a[j];
        o[j] = __floats2half2_rn(v.x * inv, v.y * inv);
    }
}

// ---------------- host ----------------
static void* sym(const void* s) { void* p = nullptr; cudaGetSymbolAddress(&p, s); return p; }

template <int MODE, bool RELU>
static void run_g(const __half* A, const __half* W, const float* bias, void* C,
                  int M, int Ntot, int K,
                  const void* idx = nullptr, long long idxoff = 0,
                  const __half* pc = nullptr, const __half* cu2 = nullptr,
                  const void* batch = nullptr) {
    static bool attr_done = false;
    if (!attr_done) {
        cudaFuncSetAttribute(k_g<MODE, RELU>, cudaFuncAttributeMaxDynamicSharedMemorySize, H_SMEM);
        attr_done = true;
    }
    dim3 grid(Ntot / 128, (M + 127) / 128);
    k_g<MODE, RELU><<<grid, 256, H_SMEM>>>(A, W, bias, C, M, Ntot, K, idx, idxoff, pc, cu2, batch);
}

extern "C" void kernel_launch(void* const* d_in, const int* in_sizes, int n_in,
                              void* d_out, int out_size) {
    const float* x    = (const float*)d_in[0];
    const void*  eidx = d_in[1];
    const float* ea   = (const float*)d_in[2];
    const float* u    = (const float*)d_in[3];
    const void*  bat  = d_in[4];
    const float* w_sel = (const float*)d_in[5];
    const float* b_sel = (const float*)d_in[6];
    const float* ew0 = (const float*)d_in[7];  const float* eb0 = (const float*)d_in[8];
    const float* ew1 = (const float*)d_in[9];  const float* eb1 = (const float*)d_in[10];
    const float* ew2 = (const float*)d_in[11]; const float* eb2 = (const float*)d_in[12];
    const float* ew3 = (const float*)d_in[13]; const float* eb3 = (const float*)d_in[14];
    const float* ew4 = (const float*)d_in[15]; const float* eb4 = (const float*)d_in[16];
    const float* nw0 = (const float*)d_in[17]; const float* nb0 = (const float*)d_in[18];
    const float* nw1 = (const float*)d_in[19]; const float* nb1 = (const float*)d_in[20];
    const float* mw0 = (const float*)d_in[21]; const float* mb0 = (const float*)d_in[22];
    const float* mw1 = (const float*)d_in[23]; const float* mb1 = (const float*)d_in[24];
    float* out = (float*)d_out;

    const int Nn = in_sizes[0] / 9;
    const int E  = in_sizes[1] / 2;
    const int B  = in_sizes[3] / USZ;

    __half* p_xpad = (__half*)sym(g_xpad);
    __half* p_pc   = (__half*)sym(g_pc);
    __half* p_ha = (__half*)sym(g_ha);
    __half* p_hb = (__half*)sym(g_hb);
    __half* p_min = (__half*)sym(g_min);
    __half* p_cu2 = (__half*)sym(g_cu2);
    float*  p_agg = (float*)sym(g_agg);
    float*  p_cnt = (float*)sym(g_cnt);
    float*  p_zb  = (float*)sym(g_zbias);
    __half* p_w1 = (__half*)sym(g_w1); __half* p_w2 = (__half*)sym(g_w2);
    __half* p_w3 = (__half*)sym(g_w3); __half* p_w4 = (__half*)sym(g_w4);
    __half* p_wn0 = (__half*)sym(g_wn0); __half* p_wn1 = (__half*)sym(g_wn1);
    __half* p_wm0 = (__half*)sym(g_wm0); __half* p_wpc = (__half*)sym(g_wpc);

    // 0. dtype detect; weight prep
    k_init_flag<<<1, 1>>>();
    k_detect<<<(E + 255) / 256, 256>>>((const long long*)eidx, E, (long long)Nn);
    k_zero<<<(PCW + 255) / 256, 256>>>(p_zb, PCW);
    k_repack16<<<(EH * EH + 255) / 256, 256>>>(ew1, p_w1, EH * EH);
    k_repack16<<<(EH * EH + 255) / 256, 256>>>(ew2, p_w2, EH * EH);
    k_repack16<<<(EH * EH + 255) / 256, 256>>>(ew3, p_w3, EH * EH);
    k_repack16<<<(EOUT * EH + 255) / 256, 256>>>(ew4, p_w4, EOUT * EH);
    k_repack16<<<(NH * NH + 255) / 256, 256>>>(nw1, p_wn1, NH * NH);
    k_repsub<<<(NH * 512 + 255) / 256, 256>>>(nw0, p_wn0, NH, 521, 9);
    k_repsub<<<(NH * 512 + 255) / 256, 256>>>(mw0, p_wm0, NH, 777, 9);
    k_build_wpc<<<(PCW * 64 + 255) / 256, 256>>>(ew0, nw0, mw0);
    k_wea<<<(EH + 255) / 256, 256>>>(ew0);

    // 1. u_r + per-graph tables
    k_ur<<<(B * URED * 32 + 255) / 256, 256>>>(u, w_sel, b_sel, B);
    k_cu<<<(BMAX * EH * 32 + 255) / 256, 256>>>(ew0, eb0);
    k_cu2<<<(BMAX * NH * 32 + 255) / 256, 256>>>(mw0, mb0);

    // 2. per-node precompute: [Pr | Pc | Qc | Rx] = xpad @ wpc^T
    k_xpad<<<(Nn * 64 + 255) / 256, 256>>>(x, Nn);
    run_g<0, false>(p_xpad, p_wpc, p_zb, p_pc, Nn, PCW, 64);

    // 3. edge layer 0 (gather-add, fused degree count) -> g_ha
    k_zero<<<(Nn + 255) / 256, 256>>>(p_cnt, Nn);
    k_edge0<<<(E * 32 + 255) / 256, 256>>>(eidx, ea, bat, p_ha, E);

    // 4. edge MLP layers 1-4
    run_g<0, true >(p_ha, p_w1, eb1, p_hb, E, EH, EH);
    run_g<0, true >(p_hb, p_w2, eb2, p_ha, E, EH, EH);
    run_g<0, true >(p_ha, p_w3, eb3, p_hb, E, EH, EH);
    run_g<0, false>(p_hb, p_w4, eb4, p_ha, E, EOUT, EH);       // edge_out, pitch 512

    // 5. node MLP1 layer 0: eout @ wn0 + Qc[col] gather
    run_g<1, true>(p_ha, p_wn0, nb0, p_hb, E, NH, NH, eidx, (long long)E, p_pc);

    // 6. node MLP1 layer 1 with fused scatter-add into agg[row]
    k_zero4<<<(Nn * NH / 4 + 255) / 256, 256>>>((float4*)p_agg, Nn * NH / 4);
    run_g<2, true>(p_hb, p_wn1, nb1, p_agg, E, NH, NH, eidx, 0);

    // 7. scatter-mean normalize -> fp16
    k_norm<<<(Nn * 32 + 255) / 256, 256>>>(Nn);

    // 8. node MLP2 with fused final 512->1 dot (bias param carries mw1)
    k_outinit<<<(Nn + 255) / 256, 256>>>(out, mb1, Nn);
    run_g<4, true>(p_min, p_wm0, mw1, out, Nn, NH, NH, nullptr, 0, p_pc, p_cu2, bat);
}

// round 16
// speedup vs baseline: 1.5756x; 1.0039x over previous
#include <cuda_runtime.h>
#include <cuda_fp16.h>
#include <cstdint>

// ---------------- Problem constants ----------------
#define EMAX 100000
#define NNMAX 20000
#define BMAX 16
#define URED 256
#define USZ 4096
#define EH 1024
#define EOUT 512
#define NH 512
#define PCW 3072          // per-node precompute: [P_r 1024 | P_c 1024 | Qc 512 | Rx 512]

// ---------------- Scratch ----------------
__device__ __align__(16) float  g_urf[BMAX * URED];
__device__ __align__(16) __half g_xpad[NNMAX * 64];
__device__ __align__(16) __half g_pc[(size_t)NNMAX * PCW];
__device__ __align__(16) __half g_cu[BMAX * EH];
__device__ __align__(16) __half g_cu2[BMAX * NH];
__device__ __align__(16) __half g_wea[EH];
__device__ __align__(16) __half g_ha[(size_t)EMAX * EH];
__device__ __align__(16) __half g_hb[(size_t)EMAX * EH];
__device__ __align__(16) float  g_agg[(size_t)NNMAX * NH];
__device__ float g_cnt[NNMAX];
__device__ __align__(16) __half g_min[(size_t)NNMAX * NH];
__device__ float g_zbias[PCW];
__device__ int   g_is64;

// fp16 weights
__device__ __align__(16) __half g_w1[EH * EH];
__device__ __align__(16) __half g_w2[EH * EH];
__device__ __align__(16) __half g_w3[EH * EH];
__device__ __align__(16) __half g_w4[EOUT * EH];
__device__ __align__(16) __half g_wn0[NH * NH];
__device__ __align__(16) __half g_wn1[NH * NH];
__device__ __align__(16) __half g_wm0[NH * NH];
__device__ __align__(16) __half g_wpc[PCW * 64];

// ---------------- helpers ----------------
__device__ __forceinline__ uint32_t smem_u32(const void* p) {
    uint32_t a;
    asm("{ .reg .u64 t; cvta.to.shared.u64 t, %1; cvt.u32.u64 %0, t; }" : "=r"(a) : "l"(p));
    return a;
}
__device__ __forceinline__ uint32_t sw128(uint32_t off) { return off ^ ((off >> 3) & 0x70); }

__global__ void k_init_flag() { g_is64 = 1; }
__global__ void k_detect(const long long* __restrict__ p, int n, long long maxv) {
    int i = blockIdx.x * blockDim.x + threadIdx.x;
    if (i < n) { long long v = p[i]; if (v < 0 || v >= maxv) g_is64 = 0; }
}
__device__ __forceinline__ long long ld_idx(const void* p, long long i) {
    if (g_is64) return ((const long long*)p)[i];
    return (long long)((const int*)p)[i];
}

// ---------------- merged prep kernel ----------------
// Segments (element index space):
//  [0,1048576)        g_w1   <- ew1
//  [1048576,2097152)  g_w2   <- ew2
//  [2097152,3145728)  g_w3   <- ew3
//  [3145728,3670016)  g_w4   <- ew4
//  [3670016,3932160)  g_wn1  <- nw1
//  [3932160,4194304)  g_wn0  <- nw0[j][9+k]  (pitch 521)
//  [4194304,4456448)  g_wm0  <- mw0[j][9+k]  (pitch 777)
//  [4456448,4653056)  g_wpc  (special build)
//  [4653056,4654080)  g_wea  <- ew0[j][18]
//  [4654080,4657152)  g_zbias = 0
//  [4657152,4657152+Nn*64) g_xpad <- x
#define PREP_W1   0
#define PREP_W2   1048576
#define PREP_W3   2097152
#define PREP_W4   3145728
#define PREP_WN1  3670016
#define PREP_WN0  3932160
#define PREP_WM0  4194304
#define PREP_WPC  4456448
#define PREP_WEA  4653056
#define PREP_ZB   4654080
#define PREP_XPAD 4657152

__global__ void k_prep(const float* __restrict__ ew0, const float* __restrict__ ew1,
                       const float* __restrict__ ew2, const float* __restrict__ ew3,
                       const float* __restrict__ ew4, const float* __restrict__ nw0,
                       const float* __restrict__ nw1, const float* __restrict__ mw0,
                       const float* __restrict__ x, int total) {
    int i = blockIdx.x * blockDim.x + threadIdx.x;
    if (i >= total) return;
    if (i < PREP_W2) {
        g_w1[i] = __float2half_rn(ew1[i]);
    } else if (i < PREP_W3) {
        int j = i - PREP_W2;  g_w2[j] = __float2half_rn(ew2[j]);
    } else if (i < PREP_W4) {
        int j = i - PREP_W3;  g_w3[j] = __float2half_rn(ew3[j]);
    } else if (i < PREP_WN1) {
        int j = i - PREP_W4;  g_w4[j] = __float2half_rn(ew4[j]);
    } else if (i < PREP_WN0) {
        int j = i - PREP_WN1; g_wn1[j] = __float2half_rn(nw1[j]);
    } else if (i < PREP_WM0) {
        int q = i - PREP_WN0; int j = q >> 9, k = q & 511;
        g_wn0[q] = __float2half_rn(nw0[(size_t)j * 521 + 9 + k]);
    } else if (i < PREP_WPC) {
        int q = i - PREP_WM0; int j = q >> 9, k = q & 511;
        g_wm0[q] = __float2half_rn(mw0[(size_t)j * 777 + 9 + k]);
    } else if (i < PREP_WEA) {
        int q = i - PREP_WPC; int j = q >> 6, c = q & 63;
        float v = 0.f;
        if (c < 9) {
            if (j < 1024)      v = ew0[(size_t)j * 275 + c];
            else if (j < 2048) v = ew0[(size_t)(j - 1024) * 275 + 9 + c];
            else if (j < 2560) v = nw0[(size_t)(j - 2048) * 521 + c];
            else               v = mw0[(size_t)(j - 2560) * 777 + c];
        }
        g_wpc[q] = __float2half_rn(v);
    } else if (i < PREP_ZB) {
        int j = i - PREP_WEA;
        g_wea[j] = __float2half_rn(ew0[(size_t)j * 275 + 18]);
    } else if (i < PREP_XPAD) {
        g_zbias[i - PREP_ZB] = 0.f;
    } else {
        int q = i - PREP_XPAD; int n = q >> 6, c = q & 63;
        g_xpad[q] = (c < 9) ? __float2half_rn(x[(size_t)n * 9 + c]) : __half(0.f);
    }
}

// ---------------- u reduction (fp32) ----------------
__global__ void k_ur(const float* __restrict__ u, const float* __restrict__ w,
                     const float* __restrict__ bias, int B) {
    int wid = (blockIdx.x * blockDim.x + threadIdx.x) >> 5;
    int lane = threadIdx.x & 31;
    if (wid >= B * URED) return;
    int b = wid >> 8, j = wid & 255;
    const float* up = u + (size_t)b * USZ;
    const float* wp = w + (size_t)j * USZ;
    float s = 0.f;
    for (int k = lane; k < USZ; k += 32) s += up[k] * wp[k];
    #pragma unroll
    for (int o = 16; o; o >>= 1) s += __shfl_down_sync(0xffffffffu, s, o);
    if (lane == 0) g_urf[wid] = s + bias[j];
}
// merged CU (16x1024 from ew0[:,19:275]) and CU2 (16x512 from mw0[:,521:777])
__global__ void k_cucu2(const float* __restrict__ ew0, const float* __restrict__ eb0,
                        const float* __restrict__ mw0, const float* __restrict__ mb0) {
    int wid = (blockIdx.x * blockDim.x + threadIdx.x) >> 5;
    int lane = threadIdx.x & 31;
    if (wid >= BMAX * (EH + NH)) return;
    float s = 0.f;
    if (wid < BMAX * EH) {
        int b = wid >> 10, j = wid & 1023;
        const float* up = g_urf + b * URED;
        const float* wp = ew0 + (size_t)j * 275 + 19;
        for (int k = lane; k < URED; k += 32) s += up[k] * wp[k];
        #pragma unroll
        for (int o = 16; o; o >>= 1) s += __shfl_down_sync(0xffffffffu, s, o);
        if (lane == 0) g_cu[wid] = __float2half_rn(s + eb0[j]);
    } else {
        int w2 = wid - BMAX * EH;
        int b = w2 >> 9, j = w2 & 511;
        const float* up = g_urf + b * URED;
        const float* wp = mw0 + (size_t)j * 777 + 521;
        for (int k = lane; k < URED; k += 32) s += up[k] * wp[k];
        #pragma unroll
        for (int o = 16; o; o >>= 1) s += __shfl_down_sync(0xffffffffu, s, o);
        if (lane == 0) g_cu2[w2] = __float2half_rn(s + mb0[j]);
    }
}

// ---------------- merged buffer init: agg=0, cnt=0, out=mb1 ----------------
__global__ void k_initbuf(float* __restrict__ out, const float* __restrict__ mb1, int Nn) {
    int i = blockIdx.x * blockDim.x + threadIdx.x;
    int nagg4 = Nn * NH / 4;
    if (i < nagg4) ((float4*)g_agg)[i] = make_float4(0.f, 0.f, 0.f, 0.f);
    if (i < Nn) { g_cnt[i] = 0.f; out[i] = mb1[0]; }
}

// ---------------- edge layer-0 (gather-add) + fused degree count ----------------
__global__ void k_edge0(const void* __restrict__ eidx, const float* __restrict__ ea,
                        const void* __restrict__ batch, __half* __restrict__ out, int E) {
    int e = (blockIdx.x * blockDim.x + threadIdx.x) >> 5;
    int lane = threadIdx.x & 31;
    if (e >= E) return;
    long long row = ld_idx(eidx, e);
    long long col = ld_idx(eidx, (long long)E + e);
    long long b = ld_idx(batch, row);
    if (lane == 0) atomicAdd(&g_cnt[row], 1.f);
    float eav = ea[e];
    const uint4* pr = (const uint4*)(g_pc + row * PCW);
    const uint4* pc = (const uint4*)(g_pc + col * PCW + 1024);
    const uint4* cu = (const uint4*)(g_cu + b * EH);
    const uint4* we = (const uint4*)g_wea;
    uint4* o = (uint4*)(out + (size_t)e * EH);
    #pragma unroll
    for (int i = 0; i < 4; i++) {
        int q = lane + i * 32;
        uint4 a4 = pr[q], b4 = pc[q], c4 = cu[q], w4 = we[q], r4;
        const __half2* ah = (const __half2*)&a4;
        const __half2* bh = (const __half2*)&b4;
        const __half2* ch = (const __half2*)&c4;
        const __half2* wh = (const __half2*)&w4;
        __half2* rh = (__half2*)&r4;
        #pragma unroll
        for (int c = 0; c < 4; c++) {
            float2 fa = __half22float2(ah[c]), fb = __half22float2(bh[c]);
            float2 fc = __half22float2(ch[c]), fw = __half22float2(wh[c]);
            float v0 = fa.x + fb.x + fc.x + eav * fw.x;
            float v1 = fa.y + fb.y + fc.y + eav * fw.y;
            v0 = v0 > 0.f ? v0 : 0.f; v1 = v1 > 0.f ? v1 : 0.f;
            rh[c] = __floats2half2_rn(v0, v1);
        }
        o[q] = r4;
    }
}

// ---------------- fp16 HMMA GEMM: CTA 128x128, warp 32x64, 2-stage (proven) ----------------
#define HTILE 16384
#define H_SMEM (4 * HTILE)         // 64 KB

__device__ __forceinline__ void ldm4(uint32_t* r, uint32_t addr) {
    asm volatile("ldmatrix.sync.aligned.m8n8.x4.shared.b16 {%0,%1,%2,%3}, [%4];"
                 : "=r"(r[0]), "=r"(r[1]), "=r"(r[2]), "=r"(r[3]) : "r"(addr));
}
__device__ __forceinline__ void mma16(float* d, const uint32_t* a, const uint32_t* b) {
    asm volatile(
        "mma.sync.aligned.m16n8k16.row.col.f32.f16.f16.f32 "
        "{%0,%1,%2,%3}, {%4,%5,%6,%7}, {%8,%9}, {%0,%1,%2,%3};"
        : "+f"(d[0]), "+f"(d[1]), "+f"(d[2]), "+f"(d[3])
        : "r"(a[0]), "r"(a[1]), "r"(a[2]), "r"(a[3]), "r"(b[0]), "r"(b[1]));
}

// MODE: 0=std store; 1=store + gather pc[idx[m]][2048+n]; 2=relu->red.v2 into agg[idx[m]];
//       4=pc[m][2560+n] + cu2[batch[m]][n] + in-register dot with bias(=mw1) -> atomicAdd out[m]
template <int MODE, bool RELU>
__global__ void __launch_bounds__(256)
k_g(const __half* __restrict__ A, const __half* __restrict__ W,
    const float* __restrict__ bias, void* __restrict__ Cv,
    int M, int Ntot, int K,
    const void* __restrict__ idx, long long idxoff,
    const __half* __restrict__ pc, const __half* __restrict__ cu2,
    const void* __restrict__ batch) {
    extern __shared__ char smem[];
    const uint32_t s_as = smem_u32(smem);
    const uint32_t s_bs = s_as + 2 * HTILE;

    const int tid = threadIdx.x;
    const int lane = tid & 31, wid = tid >> 5;
    const int warpM = wid & 3, warpN = wid >> 2;
    const size_t bm = (size_t)blockIdx.y * 128;
    const int bn = blockIdx.x * 128;
    const int nk = K >> 6;

    const int cc = tid & 7, r0 = tid >> 3;
    const int a_row = warpM * 32 + (lane & 15);
    const int a_kb  = (lane >> 4) * 16;
    const int b_row = warpN * 64 + ((lane >> 4) << 3) + (lane & 7);
    const int b_kb  = ((lane >> 3) & 1) * 16;

    float acc[2][8][4];
    #pragma unroll
    for (int i = 0; i < 2; i++)
        #pragma unroll
        for (int j = 0; j < 8; j++)
            #pragma unroll
            for (int r = 0; r < 4; r++) acc[i][j][r] = 0.f;

    auto copy_stage = [&](int kb, int buf) {
        const int kB = kb * 128;
        #pragma unroll
        for (int i = 0; i < 4; i++) {
            int r = r0 + i * 32;
            size_t mg = bm + r;
            int ok = (mg < (size_t)M) ? 16 : 0;
            const char* src = (const char*)(A + (mg < (size_t)M ? mg : 0) * K) + kB + cc * 16;
            uint32_t dst = s_as + buf * HTILE + sw128(r * 128 + cc * 16);
            asm volatile("cp.async.cg.shared.global [%0], [%1], 16, %2;"
                         :: "r"(dst), "l"(src), "r"(ok));
        }
        #pragma unroll
        for (int i = 0; i < 4; i++) {
            int r = r0 + i * 32;
            const char* src = (const char*)(W + (size_t)(bn + r) * K) + kB + cc * 16;
            uint32_t dst = s_bs + buf * HTILE + sw128(r * 128 + cc * 16);
            asm volatile("cp.async.cg.shared.global [%0], [%1], 16;" :: "r"(dst), "l"(src));
        }
        asm volatile("cp.async.commit_group;" ::: "memory");
    };

    copy_stage(0, 0);

    for (int kb = 0; kb < nk; kb++) {
        asm volatile("cp.async.wait_group 0;" ::: "memory");
        __syncthreads();
        if (kb + 1 < nk) copy_stage(kb + 1, (kb + 1) & 1);

        const uint32_t Ab = s_as + (kb & 1) * HTILE;
        const uint32_t Bb = s_bs + (kb & 1) * HTILE;

        #pragma unroll
        for (int s = 0; s < 4; s++) {
            const int ks = s * 32;
            uint32_t a[2][4];
            #pragma unroll
            for (int mt = 0; mt < 2; mt++)
                ldm4(a[mt], Ab + sw128((a_row + mt * 16) * 128 + ks + a_kb));
            #pragma unroll
            for (int p = 0; p < 4; p++) {
                uint32_t b[4];
                ldm4(b, Bb + sw128((b_row + p * 16) * 128 + ks + b_kb));
                #pragma unroll
                for (int mt = 0; mt < 2; mt++) {
                    mma16(acc[mt][2 * p],     a[mt], b);
                    mma16(acc[mt][2 * p + 1], a[mt], b + 2);
                }
            }
        }
        __syncthreads();
    }

    __half* C = (__half*)Cv;
    float* Fout = (float*)Cv;
    const int qrow = lane >> 2, qcol = (lane & 3) * 2;
    #pragma unroll
    for (int mt = 0; mt < 2; mt++) {
        #pragma unroll
        for (int hf = 0; hf < 2; hf++) {
            size_t r = bm + warpM * 32 + mt * 16 + qrow + hf * 8;
            bool okr = r < (size_t)M;
            if (MODE != 4 && !okr) continue;
            long long t = 0, bb = 0;
            if ((MODE == 1 || MODE == 2) && okr) t = ld_idx(idx, idxoff + (long long)r);
            if (MODE == 4 && okr) bb = ld_idx(batch, (long long)r);
            float partial = 0.f;
            #pragma unroll
            for (int nt = 0; nt < 8; nt++) {
                int col = bn + warpN * 64 + nt * 8 + qcol;
                float v0 = acc[mt][nt][hf * 2 + 0];
                float v1 = acc[mt][nt][hf * 2 + 1];
                if (MODE != 4) { v0 += bias[col]; v1 += bias[col + 1]; }
                if (MODE == 1) {
                    float2 g = __half22float2(*(const __half2*)(pc + (size_t)t * PCW + 2048 + col));
                    v0 += g.x; v1 += g.y;
                }
                if (MODE == 4) {
                    float2 g = okr ? __half22float2(*(const __half2*)(pc + r * PCW + 2560 + col))
                                   : make_float2(0.f, 0.f);
                    float2 c2 = okr ? __half22float2(*(const __half2*)(cu2 + bb * NH + col))
                                    : make_float2(0.f, 0.f);
                    v0 += g.x + c2.x; v1 += g.y + c2.y;
                }
                if (RELU) { v0 = v0 > 0.f ? v0 : 0.f; v1 = v1 > 0.f ? v1 : 0.f; }
                if (MODE == 4) {
                    partial += v0 * bias[col] + v1 * bias[col + 1];   // bias = mw1
                } else if (MODE == 2) {
                    float* p = Fout + (size_t)t * Ntot + col;
                    asm volatile("red.global.add.v2.f32 [%0], {%1,%2};"
                                 :: "l"(p), "f"(v0), "f"(v1) : "memory");
                } else {
                    *(__half2*)(C + r * (size_t)Ntot + col) = __floats2half2_rn(v0, v1);
                }
            }
            if (MODE == 4) {
                partial += __shfl_xor_sync(0xffffffffu, partial, 1);
                partial += __shfl_xor_sync(0xffffffffu, partial, 2);
                if (okr && (lane & 3) == 0) atomicAdd(Fout + r, partial);
            }
        }
    }
}

// ---------------- norm ----------------
__global__ void k_norm(int Nn) {
    int n = (blockIdx.x * blockDim.x + threadIdx.x) >> 5;
    int lane = threadIdx.x & 31;
    if (n >= Nn) return;
    float c = g_cnt[n];
    float inv = 1.f / (c < 1.f ? 1.f : c);
    const float2* a = (const float2*)(g_agg + (size_t)n * NH);
    __half2* o = (__half2*)(g_min + (size_t)n * NH);
    #pragma unroll
    for (int i = 0; i < 8; i++) {
        int j = lane + i * 32;
        float2 v = a[j];
        o[j] = __floats2half2_rn(v.x * inv, v.y * inv);
    }
}

// ---------------- host ----------------
static void* sym(const void* s) { void* p = nullptr; cudaGetSymbolAddress(&p, s); return p; }

template <int MODE, bool RELU>
static void run_g(const __half* A, const __half* W, const float* bias, void* C,
                  int M, int Ntot, int K,
                  const void* idx = nullptr, long long idxoff = 0,
                  const __half* pc = nullptr, const __half* cu2 = nullptr,
                  const void* batch = nullptr) {
    static bool attr_done = false;
    if (!attr_done) {
        cudaFuncSetAttribute(k_g<MODE, RELU>, cudaFuncAttributeMaxDynamicSharedMemorySize, H_SMEM);
        attr_done = true;
    }
    dim3 grid(Ntot / 128, (M + 127) / 128);
    k_g<MODE, RELU><<<grid, 256, H_SMEM>>>(A, W, bias, C, M, Ntot, K, idx, idxoff, pc, cu2, batch);
}

extern "C" void kernel_launch(void* const* d_in, const int* in_sizes, int n_in,
                              void* d_out, int out_size) {
    const float* x    = (const float*)d_in[0];
    const void*  eidx = d_in[1];
    const float* ea   = (const float*)d_in[2];
    const float* u    = (const float*)d_in[3];
    const void*  bat  = d_in[4];
    const float* w_sel = (const float*)d_in[5];
    const float* b_sel = (const float*)d_in[6];
    const float* ew0 = (const float*)d_in[7];  const float* eb0 = (const float*)d_in[8];
    const float* ew1 = (const float*)d_in[9];  const float* eb1 = (const float*)d_in[10];
    const float* ew2 = (const float*)d_in[11]; const float* eb2 = (const float*)d_in[12];
    const float* ew3 = (const float*)d_in[13]; const float* eb3 = (const float*)d_in[14];
    const float* ew4 = (const float*)d_in[15]; const float* eb4 = (const float*)d_in[16];
    const float* nw0 = (const float*)d_in[17]; const float* nb0 = (const float*)d_in[18];
    const float* nw1 = (const float*)d_in[19]; const float* nb1 = (const float*)d_in[20];
    const float* mw0 = (const float*)d_in[21]; const float* mb0 = (const float*)d_in[22];
    const float* mw1 = (const float*)d_in[23]; const float* mb1 = (const float*)d_in[24];
    float* out = (float*)d_out;

    const int Nn = in_sizes[0] / 9;
    const int E  = in_sizes[1] / 2;
    const int B  = in_sizes[3] / USZ;

    __half* p_xpad = (__half*)sym(g_xpad);
    __half* p_pc   = (__half*)sym(g_pc);
    __half* p_ha = (__half*)sym(g_ha);
    __half* p_hb = (__half*)sym(g_hb);
    __half* p_min = (__half*)sym(g_min);
    __half* p_cu2 = (__half*)sym(g_cu2);
    float*  p_agg = (float*)sym(g_agg);
    float*  p_zb  = (float*)sym(g_zbias);
    __half* p_w1 = (__half*)sym(g_w1); __half* p_w2 = (__half*)sym(g_w2);
    __half* p_w3 = (__half*)sym(g_w3); __half* p_w4 = (__half*)sym(g_w4);
    __half* p_wn0 = (__half*)sym(g_wn0); __half* p_wn1 = (__half*)sym(g_wn1);
    __half* p_wm0 = (__half*)sym(g_wm0); __half* p_wpc = (__half*)sym(g_wpc);
    (void)p_agg;

    const int prep_total = PREP_XPAD + Nn * 64;

    // launches ordered so ncu (-s 5 -c 1) captures launch #6 = first k_g
    k_init_flag<<<1, 1>>>();                                                     // 1
    k_detect<<<(E + 255) / 256, 256>>>((const long long*)eidx, E, (long long)Nn); // 2
    k_prep<<<(prep_total + 255) / 256, 256>>>(ew0, ew1, ew2, ew3, ew4,
                                              nw0, nw1, mw0, x, prep_total);     // 3
    k_ur<<<(B * URED * 32 + 255) / 256, 256>>>(u, w_sel, b_sel, B);              // 4
    k_cucu2<<<(BMAX * (EH + NH) * 32 + 255) / 256, 256>>>(ew0, eb0, mw0, mb0);   // 5

    // 2. per-node precompute: [Pr | Pc | Qc | Rx] = xpad @ wpc^T
    run_g<0, false>(p_xpad, p_wpc, p_zb, p_pc, Nn, PCW, 64);                     // 6 <- ncu lands here

    // buffer init (agg, cnt, out) before edge0/scatter
    k_initbuf<<<(Nn * NH / 4 + 255) / 256, 256>>>(out, mb1, Nn);                 // 7

    // 3. edge layer 0 (gather-add, fused degree count) -> g_ha
    k_edge0<<<(E * 32 + 255) / 256, 256>>>(eidx, ea, bat, p_ha, E);              // 8

    // 4. edge MLP layers 1-4
    run_g<0, true >(p_ha, p_w1, eb1, p_hb, E, EH, EH);
    run_g<0, true >(p_hb, p_w2, eb2, p_ha, E, EH, EH);
    run_g<0, true >(p_ha, p_w3, eb3, p_hb, E, EH, EH);
    run_g<0, false>(p_hb, p_w4, eb4, p_ha, E, EOUT, EH);       // edge_out, pitch 512

    // 5. node MLP1 layer 0: eout @ wn0 + Qc[col] gather
    run_g<1, true>(p_ha, p_wn0, nb0, p_hb, E, NH, NH, eidx, (long long)E, p_pc);

    // 6. node MLP1 layer 1 with fused scatter-add into agg[row]
    run_g<2, true>(p_hb, p_wn1, nb1, (float*)sym(g_agg), E, NH, NH, eidx, 0);

    // 7. scatter-mean normalize -> fp16
    k_norm<<<(Nn * 32 + 255) / 256, 256>>>(Nn);

    // 8. node MLP2 with fused final 512->1 dot (bias param carries mw1)
    run_g<4, true>(p_min, p_wm0, mw1, out, Nn, NH, NH, nullptr, 0, p_pc, p_cu2, bat);
}

// round 17
// speedup vs baseline: 1.5850x; 1.0060x over previous
#include <cuda_runtime.h>
#include <cuda_fp16.h>
#include <cstdint>

// ---------------- Problem constants ----------------
#define EMAX 100000
#define NNMAX 20000
#define BMAX 16
#define URED 256
#define USZ 4096
#define EH 1024
#define EOUT 512
#define NH 512
#define PCW 3072          // per-node precompute: [P_r 1024 | P_c 1024 | Qc 512 | Rx 512]

// ---------------- Scratch ----------------
__device__ __align__(16) float  g_urf[BMAX * URED];
__device__ __align__(16) __half g_xpad[NNMAX * 64];
__device__ __align__(16) __half g_pc[(size_t)NNMAX * PCW];
__device__ __align__(16) __half g_cu[BMAX * EH];
__device__ __align__(16) __half g_cu2[BMAX * NH];
__device__ __align__(16) __half g_wea[EH];
__device__ __align__(16) __half g_ha[(size_t)EMAX * EH];
__device__ __align__(16) __half g_hb[(size_t)EMAX * EH];
__device__ __align__(16) float  g_agg[(size_t)NNMAX * NH];
__device__ float g_cnt[NNMAX];
__device__ __align__(16) __half g_min[(size_t)NNMAX * NH];
__device__ float g_zbias[PCW];
__device__ int   g_is64;

// fp16 weights
__device__ __align__(16) __half g_w1[EH * EH];
__device__ __align__(16) __half g_w2[EH * EH];
__device__ __align__(16) __half g_w3[EH * EH];
__device__ __align__(16) __half g_w4[EOUT * EH];
__device__ __align__(16) __half g_wn0[NH * NH];
__device__ __align__(16) __half g_wn1[NH * NH];
__device__ __align__(16) __half g_wm0[NH * NH];
__device__ __align__(16) __half g_wpc[PCW * 64];

// ---------------- helpers ----------------
__device__ __forceinline__ uint32_t smem_u32(const void* p) {
    uint32_t a;
    asm("{ .reg .u64 t; cvta.to.shared.u64 t, %1; cvt.u32.u64 %0, t; }" : "=r"(a) : "l"(p));
    return a;
}
__device__ __forceinline__ uint32_t sw128(uint32_t off) { return off ^ ((off >> 3) & 0x70); }

__global__ void k_init_flag() { g_is64 = 1; }
__global__ void k_detect(const long long* __restrict__ p, int n, long long maxv) {
    int i = blockIdx.x * blockDim.x + threadIdx.x;
    if (i < n) { long long v = p[i]; if (v < 0 || v >= maxv) g_is64 = 0; }
}
__device__ __forceinline__ long long ld_idx(const void* p, long long i) {
    if (g_is64) return ((const long long*)p)[i];
    return (long long)((const int*)p)[i];
}

// ---------------- merged prep kernel ----------------
#define PREP_W1   0
#define PREP_W2   1048576
#define PREP_W3   2097152
#define PREP_W4   3145728
#define PREP_WN1  3670016
#define PREP_WN0  3932160
#define PREP_WM0  4194304
#define PREP_WPC  4456448
#define PREP_WEA  4653056
#define PREP_ZB   4654080
#define PREP_XPAD 4657152

__global__ void k_prep(const float* __restrict__ ew0, const float* __restrict__ ew1,
                       const float* __restrict__ ew2, const float* __restrict__ ew3,
                       const float* __restrict__ ew4, const float* __restrict__ nw0,
                       const float* __restrict__ nw1, const float* __restrict__ mw0,
                       const float* __restrict__ x, int total) {
    int i = blockIdx.x * blockDim.x + threadIdx.x;
    if (i >= total) return;
    if (i < PREP_W2) {
        g_w1[i] = __float2half_rn(ew1[i]);
    } else if (i < PREP_W3) {
        int j = i - PREP_W2;  g_w2[j] = __float2half_rn(ew2[j]);
    } else if (i < PREP_W4) {
        int j = i - PREP_W3;  g_w3[j] = __float2half_rn(ew3[j]);
    } else if (i < PREP_WN1) {
        int j = i - PREP_W4;  g_w4[j] = __float2half_rn(ew4[j]);
    } else if (i < PREP_WN0) {
        int j = i - PREP_WN1; g_wn1[j] = __float2half_rn(nw1[j]);
    } else if (i < PREP_WM0) {
        int q = i - PREP_WN0; int j = q >> 9, k = q & 511;
        g_wn0[q] = __float2half_rn(nw0[(size_t)j * 521 + 9 + k]);
    } else if (i < PREP_WPC) {
        int q = i - PREP_WM0; int j = q >> 9, k = q & 511;
        g_wm0[q] = __float2half_rn(mw0[(size_t)j * 777 + 9 + k]);
    } else if (i < PREP_WEA) {
        int q = i - PREP_WPC; int j = q >> 6, c = q & 63;
        float v = 0.f;
        if (c < 9) {
            if (j < 1024)      v = ew0[(size_t)j * 275 + c];
            else if (j < 2048) v = ew0[(size_t)(j - 1024) * 275 + 9 + c];
            else if (j < 2560) v = nw0[(size_t)(j - 2048) * 521 + c];
            else               v = mw0[(size_t)(j - 2560) * 777 + c];
        }
        g_wpc[q] = __float2half_rn(v);
    } else if (i < PREP_ZB) {
        int j = i - PREP_WEA;
        g_wea[j] = __float2half_rn(ew0[(size_t)j * 275 + 18]);
    } else if (i < PREP_XPAD) {
        g_zbias[i - PREP_ZB] = 0.f;
    } else {
        int q = i - PREP_XPAD; int n = q >> 6, c = q & 63;
        g_xpad[q] = (c < 9) ? __float2half_rn(x[(size_t)n * 9 + c]) : __half(0.f);
    }
}

// ---------------- u reduction (fp32) ----------------
__global__ void k_ur(const float* __restrict__ u, const float* __restrict__ w,
                     const float* __restrict__ bias, int B) {
    int wid = (blockIdx.x * blockDim.x + threadIdx.x) >> 5;
    int lane = threadIdx.x & 31;
    if (wid >= B * URED) return;
    int b = wid >> 8, j = wid & 255;
    const float* up = u + (size_t)b * USZ;
    const float* wp = w + (size_t)j * USZ;
    float s = 0.f;
    for (int k = lane; k < USZ; k += 32) s += up[k] * wp[k];
    #pragma unroll
    for (int o = 16; o; o >>= 1) s += __shfl_down_sync(0xffffffffu, s, o);
    if (lane == 0) g_urf[wid] = s + bias[j];
}
// merged CU (16x1024 from ew0[:,19:275]) and CU2 (16x512 from mw0[:,521:777])
__global__ void k_cucu2(const float* __restrict__ ew0, const float* __restrict__ eb0,
                        const float* __restrict__ mw0, const float* __restrict__ mb0) {
    int wid = (blockIdx.x * blockDim.x + threadIdx.x) >> 5;
    int lane = threadIdx.x & 31;
    if (wid >= BMAX * (EH + NH)) return;
    float s = 0.f;
    if (wid < BMAX * EH) {
        int b = wid >> 10, j = wid & 1023;
        const float* up = g_urf + b * URED;
        const float* wp = ew0 + (size_t)j * 275 + 19;
        for (int k = lane; k < URED; k += 32) s += up[k] * wp[k];
        #pragma unroll
        for (int o = 16; o; o >>= 1) s += __shfl_down_sync(0xffffffffu, s, o);
        if (lane == 0) g_cu[wid] = __float2half_rn(s + eb0[j]);
    } else {
        int w2 = wid - BMAX * EH;
        int b = w2 >> 9, j = w2 & 511;
        const float* up = g_urf + b * URED;
        const float* wp = mw0 + (size_t)j * 777 + 521;
        for (int k = lane; k < URED; k += 32) s += up[k] * wp[k];
        #pragma unroll
        for (int o = 16; o; o >>= 1) s += __shfl_down_sync(0xffffffffu, s, o);
        if (lane == 0) g_cu2[w2] = __float2half_rn(s + mb0[j]);
    }
}

// ---------------- merged buffer init: agg=0, cnt=0, out=mb1 ----------------
__global__ void k_initbuf(float* __restrict__ out, const float* __restrict__ mb1, int Nn) {
    int i = blockIdx.x * blockDim.x + threadIdx.x;
    int nagg4 = Nn * NH / 4;
    if (i < nagg4) ((float4*)g_agg)[i] = make_float4(0.f, 0.f, 0.f, 0.f);
    if (i < Nn) { g_cnt[i] = 0.f; out[i] = mb1[0]; }
}

// ---------------- edge layer-0 (gather-add) + fused degree count ----------------
__global__ void k_edge0(const void* __restrict__ eidx, const float* __restrict__ ea,
                        const void* __restrict__ batch, __half* __restrict__ out, int E) {
    int e = (blockIdx.x * blockDim.x + threadIdx.x) >> 5;
    int lane = threadIdx.x & 31;
    if (e >= E) return;
    long long row = ld_idx(eidx, e);
    long long col = ld_idx(eidx, (long long)E + e);
    long long b = ld_idx(batch, row);
    if (lane == 0) atomicAdd(&g_cnt[row], 1.f);
    float eav = ea[e];
    const uint4* pr = (const uint4*)(g_pc + row * PCW);
    const uint4* pc = (const uint4*)(g_pc + col * PCW + 1024);
    const uint4* cu = (const uint4*)(g_cu + b * EH);
    const uint4* we = (const uint4*)g_wea;
    uint4* o = (uint4*)(out + (size_t)e * EH);
    #pragma unroll
    for (int i = 0; i < 4; i++) {
        int q = lane + i * 32;
        uint4 a4 = pr[q], b4 = pc[q], c4 = cu[q], w4 = we[q], r4;
        const __half2* ah = (const __half2*)&a4;
        const __half2* bh = (const __half2*)&b4;
        const __half2* ch = (const __half2*)&c4;
        const __half2* wh = (const __half2*)&w4;
        __half2* rh = (__half2*)&r4;
        #pragma unroll
        for (int c = 0; c < 4; c++) {
            float2 fa = __half22float2(ah[c]), fb = __half22float2(bh[c]);
            float2 fc = __half22float2(ch[c]), fw = __half22float2(wh[c]);
            float v0 = fa.x + fb.x + fc.x + eav * fw.x;
            float v1 = fa.y + fb.y + fc.y + eav * fw.y;
            v0 = v0 > 0.f ? v0 : 0.f; v1 = v1 > 0.f ? v1 : 0.f;
            rh[c] = __floats2half2_rn(v0, v1);
        }
        o[q] = r4;
    }
}

// ---------------- fp16 HMMA GEMM: CTA 128x128, warp 32x64, 2-stage, 1 barrier/ktile ----------------
#define HTILE 16384
#define H_SMEM (4 * HTILE)         // 64 KB

__device__ __forceinline__ void ldm4(uint32_t* r, uint32_t addr) {
    asm volatile("ldmatrix.sync.aligned.m8n8.x4.shared.b16 {%0,%1,%2,%3}, [%4];"
                 : "=r"(r[0]), "=r"(r[1]), "=r"(r[2]), "=r"(r[3]) : "r"(addr));
}
__device__ __forceinline__ void mma16(float* d, const uint32_t* a, const uint32_t* b) {
    asm volatile(
        "mma.sync.aligned.m16n8k16.row.col.f32.f16.f16.f32 "
        "{%0,%1,%2,%3}, {%4,%5,%6,%7}, {%8,%9}, {%0,%1,%2,%3};"
        : "+f"(d[0]), "+f"(d[1]), "+f"(d[2]), "+f"(d[3])
        : "r"(a[0]), "r"(a[1]), "r"(a[2]), "r"(a[3]), "r"(b[0]), "r"(b[1]));
}

// MODE: 0=std store; 1=store + gather pc[idx[m]][2048+n]; 2=relu->red.v2 into agg[idx[m]];
//       4=pc[m][2560+n] + cu2[batch[m]][n] + in-register dot with bias(=mw1) -> atomicAdd out[m]
template <int MODE, bool RELU>
__global__ void __launch_bounds__(256)
k_g(const __half* __restrict__ A, const __half* __restrict__ W,
    const float* __restrict__ bias, void* __restrict__ Cv,
    int M, int Ntot, int K,
    const void* __restrict__ idx, long long idxoff,
    const __half* __restrict__ pc, const __half* __restrict__ cu2,
    const void* __restrict__ batch) {
    extern __shared__ char smem[];
    const uint32_t s_as = smem_u32(smem);
    const uint32_t s_bs = s_as + 2 * HTILE;

    const int tid = threadIdx.x;
    const int lane = tid & 31, wid = tid >> 5;
    const int warpM = wid & 3, warpN = wid >> 2;
    const size_t bm = (size_t)blockIdx.y * 128;
    const int bn = blockIdx.x * 128;
    const int nk = K >> 6;

    const int cc = tid & 7, r0 = tid >> 3;
    const int a_row = warpM * 32 + (lane & 15);
    const int a_kb  = (lane >> 4) * 16;
    const int b_row = warpN * 64 + ((lane >> 4) << 3) + (lane & 7);
    const int b_kb  = ((lane >> 3) & 1) * 16;

    float acc[2][8][4];
    #pragma unroll
    for (int i = 0; i < 2; i++)
        #pragma unroll
        for (int j = 0; j < 8; j++)
            #pragma unroll
            for (int r = 0; r < 4; r++) acc[i][j][r] = 0.f;

    auto copy_stage = [&](int kb, int buf) {
        const int kB = kb * 128;
        #pragma unroll
        for (int i = 0; i < 4; i++) {
            int r = r0 + i * 32;
            size_t mg = bm + r;
            int ok = (mg < (size_t)M) ? 16 : 0;
            const char* src = (const char*)(A + (mg < (size_t)M ? mg : 0) * K) + kB + cc * 16;
            uint32_t dst = s_as + buf * HTILE + sw128(r * 128 + cc * 16);
            asm volatile("cp.async.cg.shared.global [%0], [%1], 16, %2;"
                         :: "r"(dst), "l"(src), "r"(ok));
        }
        #pragma unroll
        for (int i = 0; i < 4; i++) {
            int r = r0 + i * 32;
            const char* src = (const char*)(W + (size_t)(bn + r) * K) + kB + cc * 16;
            uint32_t dst = s_bs + buf * HTILE + sw128(r * 128 + cc * 16);
            asm volatile("cp.async.cg.shared.global [%0], [%1], 16;" :: "r"(dst), "l"(src));
        }
        asm volatile("cp.async.commit_group;" ::: "memory");
    };

    copy_stage(0, 0);

    for (int kb = 0; kb < nk; kb++) {
        asm volatile("cp.async.wait_group 0;" ::: "memory");
        __syncthreads();
        // Safe to overwrite buf (kb+1)&1 (held stage kb-1): every warp finished
        // compute(kb-1) before reaching the barrier above (program order), and
        // the barrier is collective — no end-of-loop barrier needed.
        if (kb + 1 < nk) copy_stage(kb + 1, (kb + 1) & 1);

        const uint32_t Ab = s_as + (kb & 1) * HTILE;
        const uint32_t Bb = s_bs + (kb & 1) * HTILE;

        #pragma unroll
        for (int s = 0; s < 4; s++) {
            const int ks = s * 32;
            uint32_t a[2][4];
            #pragma unroll
            for (int mt = 0; mt < 2; mt++)
                ldm4(a[mt], Ab + sw128((a_row + mt * 16) * 128 + ks + a_kb));
            #pragma unroll
            for (int p = 0; p < 4; p++) {
                uint32_t b[4];
                ldm4(b, Bb + sw128((b_row + p * 16) * 128 + ks + b_kb));
                #pragma unroll
                for (int mt = 0; mt < 2; mt++) {
                    mma16(acc[mt][2 * p],     a[mt], b);
                    mma16(acc[mt][2 * p + 1], a[mt], b + 2);
                }
            }
        }
    }

    __half* C = (__half*)Cv;
    float* Fout = (float*)Cv;
    const int qrow = lane >> 2, qcol = (lane & 3) * 2;
    #pragma unroll
    for (int mt = 0; mt < 2; mt++) {
        #pragma unroll
        for (int hf = 0; hf < 2; hf++) {
            size_t r = bm + warpM * 32 + mt * 16 + qrow + hf * 8;
            bool okr = r < (size_t)M;
            if (MODE != 4 && !okr) continue;
            long long t = 0, bb = 0;
            if ((MODE == 1 || MODE == 2) && okr) t = ld_idx(idx, idxoff + (long long)r);
            if (MODE == 4 && okr) bb = ld_idx(batch, (long long)r);
            float partial = 0.f;
            #pragma unroll
            for (int nt = 0; nt < 8; nt++) {
                int col = bn + warpN * 64 + nt * 8 + qcol;
                float v0 = acc[mt][nt][hf * 2 + 0];
                float v1 = acc[mt][nt][hf * 2 + 1];
                if (MODE != 4) { v0 += bias[col]; v1 += bias[col + 1]; }
                if (MODE == 1) {
                    float2 g = __half22float2(*(const __half2*)(pc + (size_t)t * PCW + 2048 + col));
                    v0 += g.x; v1 += g.y;
                }
                if (MODE == 4) {
                    float2 g = okr ? __half22float2(*(const __half2*)(pc + r * PCW + 2560 + col))
                                   : make_float2(0.f, 0.f);
                    float2 c2 = okr ? __half22float2(*(const __half2*)(cu2 + bb * NH + col))
                                    : make_float2(0.f, 0.f);
                    v0 += g.x + c2.x; v1 += g.y + c2.y;
                }
                if (RELU) { v0 = v0 > 0.f ? v0 : 0.f; v1 = v1 > 0.f ? v1 : 0.f; }
                if (MODE == 4) {
                    partial += v0 * bias[col] + v1 * bias[col + 1];   // bias = mw1
                } else if (MODE == 2) {
                    float* p = Fout + (size_t)t * Ntot + col;
                    asm volatile("red.global.add.v2.f32 [%0], {%1,%2};"
                                 :: "l"(p), "f"(v0), "f"(v1) : "memory");
                } else {
                    *(__half2*)(C + r * (size_t)Ntot + col) = __floats2half2_rn(v0, v1);
                }
            }
            if (MODE == 4) {
                partial += __shfl_xor_sync(0xffffffffu, partial, 1);
                partial += __shfl_xor_sync(0xffffffffu, partial, 2);
                if (okr && (lane & 3) == 0) atomicAdd(Fout + r, partial);
            }
        }
    }
}

// ---------------- norm ----------------
__global__ void k_norm(int Nn) {
    int n = (blockIdx.x * blockDim.x + threadIdx.x) >> 5;
    int lane = threadIdx.x & 31;
    if (n >= Nn) return;
    float c = g_cnt[n];
    float inv = 1.f / (c < 1.f ? 1.f : c);
    const float2* a = (const float2*)(g_agg + (size_t)n * NH);
    __half2* o = (__half2*)(g_min + (size_t)n * NH);
    #pragma unroll
    for (int i = 0; i < 8; i++) {
        int j = lane + i * 32;
        float2 v = a[j];
        o[j] = __floats2half2_rn(v.x * inv, v.y * inv);
    }
}

// ---------------- host ----------------
static void* sym(const void* s) { void* p = nullptr; cudaGetSymbolAddress(&p, s); return p; }

template <int MODE, bool RELU>
static void run_g(const __half* A, const __half* W, const float* bias, void* C,
                  int M, int Ntot, int K,
                  const void* idx = nullptr, long long idxoff = 0,
                  const __half* pc = nullptr, const __half* cu2 = nullptr,
                  const void* batch = nullptr) {
    static bool attr_done = false;
    if (!attr_done) {
        cudaFuncSetAttribute(k_g<MODE, RELU>, cudaFuncAttributeMaxDynamicSharedMemorySize, H_SMEM);
        attr_done = true;
    }
    dim3 grid(Ntot / 128, (M + 127) / 128);
    k_g<MODE, RELU><<<grid, 256, H_SMEM>>>(A, W, bias, C, M, Ntot, K, idx, idxoff, pc, cu2, batch);
}

extern "C" void kernel_launch(void* const* d_in, const int* in_sizes, int n_in,
                              void* d_out, int out_size) {
    const float* x    = (const float*)d_in[0];
    const void*  eidx = d_in[1];
    const float* ea   = (const float*)d_in[2];
    const float* u    = (const float*)d_in[3];
    const void*  bat  = d_in[4];
    const float* w_sel = (const float*)d_in[5];
    const float* b_sel = (const float*)d_in[6];
    const float* ew0 = (const float*)d_in[7];  const float* eb0 = (const float*)d_in[8];
    const float* ew1 = (const float*)d_in[9];  const float* eb1 = (const float*)d_in[10];
    const float* ew2 = (const float*)d_in[11]; const float* eb2 = (const float*)d_in[12];
    const float* ew3 = (const float*)d_in[13]; const float* eb3 = (const float*)d_in[14];
    const float* ew4 = (const float*)d_in[15]; const float* eb4 = (const float*)d_in[16];
    const float* nw0 = (const float*)d_in[17]; const float* nb0 = (const float*)d_in[18];
    const float* nw1 = (const float*)d_in[19]; const float* nb1 = (const float*)d_in[20];
    const float* mw0 = (const float*)d_in[21]; const float* mb0 = (const float*)d_in[22];
    const float* mw1 = (const float*)d_in[23]; const float* mb1 = (const float*)d_in[24];
    float* out = (float*)d_out;

    const int Nn = in_sizes[0] / 9;
    const int E  = in_sizes[1] / 2;
    const int B  = in_sizes[3] / USZ;

    __half* p_xpad = (__half*)sym(g_xpad);
    __half* p_pc   = (__half*)sym(g_pc);
    __half* p_ha = (__half*)sym(g_ha);
    __half* p_hb = (__half*)sym(g_hb);
    __half* p_min = (__half*)sym(g_min);
    __half* p_cu2 = (__half*)sym(g_cu2);
    float*  p_zb  = (float*)sym(g_zbias);
    __half* p_w1 = (__half*)sym(g_w1); __half* p_w2 = (__half*)sym(g_w2);
    __half* p_w3 = (__half*)sym(g_w3); __half* p_w4 = (__half*)sym(g_w4);
    __half* p_wn0 = (__half*)sym(g_wn0); __half* p_wn1 = (__half*)sym(g_wn1);
    __half* p_wm0 = (__half*)sym(g_wm0); __half* p_wpc = (__half*)sym(g_wpc);

    const int prep_total = PREP_XPAD + Nn * 64;

    k_init_flag<<<1, 1>>>();
    k_detect<<<(E + 255) / 256, 256>>>((const long long*)eidx, E, (long long)Nn);
    k_prep<<<(prep_total + 255) / 256, 256>>>(ew0, ew1, ew2, ew3, ew4,
                                              nw0, nw1, mw0, x, prep_total);
    k_ur<<<(B * URED * 32 + 255) / 256, 256>>>(u, w_sel, b_sel, B);
    k_cucu2<<<(BMAX * (EH + NH) * 32 + 255) / 256, 256>>>(ew0, eb0, mw0, mb0);

    // per-node precompute: [Pr | Pc | Qc | Rx] = xpad @ wpc^T
    run_g<0, false>(p_xpad, p_wpc, p_zb, p_pc, Nn, PCW, 64);

    // buffer init (agg, cnt, out)
    k_initbuf<<<(Nn * NH / 4 + 255) / 256, 256>>>(out, mb1, Nn);

    // edge layer 0 (gather-add, fused degree count) -> g_ha
    k_edge0<<<(E * 32 + 255) / 256, 256>>>(eidx, ea, bat, p_ha, E);

    // edge MLP layers 1-4
    run_g<0, true >(p_ha, p_w1, eb1, p_hb, E, EH, EH);
    run_g<0, true >(p_hb, p_w2, eb2, p_ha, E, EH, EH);
    run_g<0, true >(p_ha, p_w3, eb3, p_hb, E, EH, EH);
    run_g<0, false>(p_hb, p_w4, eb4, p_ha, E, EOUT, EH);       // edge_out, pitch 512

    // node MLP1 layer 0: eout @ wn0 + Qc[col] gather
    run_g<1, true>(p_ha, p_wn0, nb0, p_hb, E, NH, NH, eidx, (long long)E, p_pc);

    // node MLP1 layer 1 with fused scatter-add into agg[row]
    run_g<2, true>(p_hb, p_wn1, nb1, (float*)sym(g_agg), E, NH, NH, eidx, 0);

    // scatter-mean normalize -> fp16
    k_norm<<<(Nn * 32 + 255) / 256, 256>>>(Nn);

    // node MLP2 with fused final 512->1 dot (bias param carries mw1)
    run_g<4, true>(p_min, p_wm0, mw1, out, Nn, NH, NH, nullptr, 0, p_pc, p_cu2, bat);
}